// round 1
// baseline (speedup 1.0000x reference)
#include <cuda_runtime.h>
#include <math.h>

// Problem constants (fixed by setup_inputs)
#define B 4
#define H 320
#define W 320
#define NPIX (B * H * W)
#define LAMBDA 1.0f

// Scratch: squared 1D vertical distance g2[b,h,w]
__device__ float g_g2[NPIX];
// Global loss accumulator (double for safe accumulation across 1280 blocks)
__device__ double g_acc;

// ---------------------------------------------------------------------------
// Kernel 1: vertical distance pass. One thread per (b, w) column.
// Forward scan: distance to nearest seed above. Backward: min with seed below,
// then square. Consecutive threads touch consecutive w -> coalesced.
// Also zeroes the accumulator (safe: kernel 2 is stream-ordered after us).
// ---------------------------------------------------------------------------
__global__ void edt_vertical_kernel(const int* __restrict__ targets)
{
    int idx = blockIdx.x * blockDim.x + threadIdx.x;
    if (idx == 0) g_acc = 0.0;
    if (idx >= B * W) return;

    int b = idx / W;
    int w = idx - b * W;
    const int* col = targets + (size_t)b * H * W + w;
    float*       g = g_g2    + (size_t)b * H * W + w;

    // Forward: d_up = h - last_seed_row (inf if none yet)
    float last = -INFINITY;
    #pragma unroll 4
    for (int h = 0; h < H; ++h) {
        if (col[h * W] != 0) last = (float)h;
        g[h * W] = (float)h - last;
    }
    // Backward: min with next_seed_row - h, then square
    float next = INFINITY;
    #pragma unroll 4
    for (int h = H - 1; h >= 0; --h) {
        if (col[h * W] != 0) next = (float)h;
        float d = fminf(g[h * W], next - (float)h);
        g[h * W] = d * d;
    }
}

// ---------------------------------------------------------------------------
// Kernel 2: horizontal pass + fused loss.
// One block per (b, h) row. Row of g2 staged in smem. For each output column
// wo: best = min_wi (wo-wi)^2 + g2[wi], computed by outward search with
// pruning (once r^2 >= best, no further wi can improve since g2 >= 0).
// Then fuse sigmoid(logit), sqrt, per-pixel contribution, block-reduce, and
// atomicAdd into the global accumulator. d2 never touches global memory.
// ---------------------------------------------------------------------------
__global__ void edt_horizontal_loss_kernel(const float* __restrict__ logits)
{
    __shared__ float s[W];
    __shared__ float warp_sums[W / 32];

    int row = blockIdx.x;              // 0 .. B*H-1
    int wo  = threadIdx.x;             // 0 .. W-1
    const size_t base = (size_t)row * W;

    s[wo] = g_g2[base + wo];
    __syncthreads();

    // Pruned outward min search
    float best = s[wo];
    for (int r = 1; r < W; ++r) {
        float rr = (float)(r * r);
        if (rr >= best) break;
        int lo = wo - r;
        int hi = wo + r;
        if (lo >= 0) best = fminf(best, s[lo] + rr);
        if (hi < W)  best = fminf(best, s[hi] + rr);
    }

    float d = sqrtf(best);
    float x = logits[base + wo];
    float p = 1.0f / (1.0f + __expf(-x));
    float contrib = p * d + LAMBDA * (1.0f - p);

    // Warp reduce
    for (int off = 16; off > 0; off >>= 1)
        contrib += __shfl_down_sync(0xFFFFFFFFu, contrib, off);

    int lane = wo & 31;
    int wid  = wo >> 5;
    if (lane == 0) warp_sums[wid] = contrib;
    __syncthreads();

    if (wid == 0) {
        float v = (lane < (W / 32)) ? warp_sums[lane] : 0.0f;
        for (int off = 16; off > 0; off >>= 1)
            v += __shfl_down_sync(0xFFFFFFFFu, v, off);
        if (lane == 0) atomicAdd(&g_acc, (double)v);
    }
}

// ---------------------------------------------------------------------------
// Kernel 3: finalize scalar output.
// ---------------------------------------------------------------------------
__global__ void finalize_kernel(float* __restrict__ out)
{
    out[0] = (float)(g_acc / (double)NPIX);
}

extern "C" void kernel_launch(void* const* d_in, const int* in_sizes, int n_in,
                              void* d_out, int out_size)
{
    const float* logits  = (const float*)d_in[0];
    const int*   targets = (const int*)d_in[1];
    float*       out     = (float*)d_out;

    (void)in_sizes; (void)n_in; (void)out_size;

    // Kernel 1: B*W = 1280 column threads
    edt_vertical_kernel<<<(B * W + 255) / 256, 256>>>(targets);
    // Kernel 2: one block per row
    edt_horizontal_loss_kernel<<<B * H, W>>>(logits);
    // Kernel 3: scalar finalize
    finalize_kernel<<<1, 1>>>(out);
}

// round 2
// speedup vs baseline: 3.2657x; 3.2657x over previous
#include <cuda_runtime.h>
#include <math.h>

// Problem constants (fixed by setup_inputs)
#define B 4
#define H 320
#define W 320
#define NPIX (B * H * W)
#define LAMBDA 1.0f

// Global loss accumulator (double, reset by finalize each call -> replay-safe)
__device__ double g_acc;

// ---------------------------------------------------------------------------
// Fused kernel: one block per (b, h) row, W threads.
//  1. Per-thread pruned OUTWARD vertical search over targets column:
//     g2[w] = (nearest seed distance in column)^2  -> shared memory.
//     With ~50% seed density this terminates in ~1-4 iterations.
//  2. Pruned horizontal min over smem: d2 = min_wi (wo-wi)^2 + g2[wi].
//  3. Fused sigmoid/sqrt/loss + block reduction + atomicAdd(double).
// No intermediate tensors ever touch global memory.
// ---------------------------------------------------------------------------
__global__ void __launch_bounds__(W)
edt_fused_loss_kernel(const float* __restrict__ logits,
                      const int*   __restrict__ targets)
{
    __shared__ float s[W];
    __shared__ float warp_sums[W / 32];

    const int row = blockIdx.x;          // 0 .. B*H-1
    const int b   = row / H;
    const int h   = row - b * H;
    const int wo  = threadIdx.x;         // 0 .. W-1
    const size_t img_base = (size_t)b * H * W;
    const size_t row_base = (size_t)row * W;

    // Prefetch logit early (independent of the searches)
    const float x = logits[row_base + wo];

    // --- 1. Vertical outward search (first hit is the minimum) ---
    const int* tcol = targets + img_base + wo;   // column w = wo
    float vbest = INFINITY;                      // squared vertical distance
    for (int r = 0; r < H; ++r) {
        const int hu = h - r;
        const int hd = h + r;
        bool found = false;
        if (hu >= 0 && tcol[hu * W] != 0) found = true;
        if (hd < H  && tcol[hd * W] != 0) found = true;
        if (found) { vbest = (float)(r * r); break; }
    }
    s[wo] = vbest;
    __syncthreads();

    // --- 2. Pruned horizontal min search over smem ---
    float best = vbest;
    for (int r = 1; r < W; ++r) {
        const float rr = (float)(r * r);
        if (rr >= best) break;
        const int lo = wo - r;
        const int hi = wo + r;
        if (lo >= 0) best = fminf(best, s[lo] + rr);
        if (hi < W)  best = fminf(best, s[hi] + rr);
    }

    // --- 3. Fused loss ---
    const float d = sqrtf(best);
    const float p = 1.0f / (1.0f + __expf(-x));
    float contrib = p * d + LAMBDA * (1.0f - p);

    // Warp reduce
    #pragma unroll
    for (int off = 16; off > 0; off >>= 1)
        contrib += __shfl_down_sync(0xFFFFFFFFu, contrib, off);

    const int lane = wo & 31;
    const int wid  = wo >> 5;
    if (lane == 0) warp_sums[wid] = contrib;
    __syncthreads();

    if (wid == 0) {
        float v = (lane < (W / 32)) ? warp_sums[lane] : 0.0f;
        #pragma unroll
        for (int off = 16; off > 0; off >>= 1)
            v += __shfl_down_sync(0xFFFFFFFFu, v, off);
        if (lane == 0) atomicAdd(&g_acc, (double)v);
    }
}

// ---------------------------------------------------------------------------
// Finalize: write mean, then reset accumulator so every graph replay starts
// from the same state (g_acc is zero-initialized at load).
// ---------------------------------------------------------------------------
__global__ void finalize_kernel(float* __restrict__ out)
{
    out[0] = (float)(g_acc / (double)NPIX);
    g_acc = 0.0;
}

extern "C" void kernel_launch(void* const* d_in, const int* in_sizes, int n_in,
                              void* d_out, int out_size)
{
    const float* logits  = (const float*)d_in[0];
    const int*   targets = (const int*)d_in[1];
    float*       out     = (float*)d_out;

    (void)in_sizes; (void)n_in; (void)out_size;

    edt_fused_loss_kernel<<<B * H, W>>>(logits, targets);
    finalize_kernel<<<1, 1>>>(out);
}

// round 3
// speedup vs baseline: 3.8780x; 1.1875x over previous
#include <cuda_runtime.h>
#include <math.h>

// Problem constants (fixed by setup_inputs)
#define B 4
#define H 320
#define W 320
#define NPIX (B * H * W)
#define NROWS (B * H)
#define LAMBDA 1.0f

// Global accumulator + completion counter (reset by last block -> replay-safe)
__device__ double g_acc;
__device__ unsigned int g_count;

// ---------------------------------------------------------------------------
// Single fused kernel: one block per (b, h) row, W threads.
//  1. Vertical nearest-seed search: batched probes r=0..4 issued as 9
//     independent coalesced loads (one L2 round-trip), ALU-only first-hit
//     resolve; rare fallback loop for r>=5 (P ~ 0.2% per pixel).
//  2. Pruned horizontal min over smem: d2 = min_wi (wo-wi)^2 + g2[wi].
//  3. Fused sigmoid/sqrt/loss, block reduce, atomicAdd(double), and
//     last-block finalize (writes mean to out, resets globals).
// ---------------------------------------------------------------------------
__global__ void __launch_bounds__(W)
edt_fused_loss_kernel(const float* __restrict__ logits,
                      const int*   __restrict__ targets,
                      float*       __restrict__ out)
{
    __shared__ float s[W];
    __shared__ float warp_sums[W / 32];

    const int row = blockIdx.x;          // 0 .. B*H-1
    const int b   = row / H;
    const int h   = row - b * H;
    const int wo  = threadIdx.x;         // 0 .. W-1
    const size_t img_base = (size_t)b * H * W;
    const size_t row_base = (size_t)row * W;

    // Independent of the searches -> issue early
    const float x = logits[row_base + wo];

    const int* tcol = targets + img_base + wo;   // column w = wo

    // --- 1. Vertical search: batched probes r=0..4 (9 independent loads) ---
    int t0  = tcol[h * W];
    int u1 = 0, u2 = 0, u3 = 0, u4 = 0;
    int d1 = 0, d2v = 0, d3 = 0, d4 = 0;
    if (h - 1 >= 0) u1 = tcol[(h - 1) * W];
    if (h - 2 >= 0) u2 = tcol[(h - 2) * W];
    if (h - 3 >= 0) u3 = tcol[(h - 3) * W];
    if (h - 4 >= 0) u4 = tcol[(h - 4) * W];
    if (h + 1 < H)  d1 = tcol[(h + 1) * W];
    if (h + 2 < H)  d2v = tcol[(h + 2) * W];
    if (h + 3 < H)  d3 = tcol[(h + 3) * W];
    if (h + 4 < H)  d4 = tcol[(h + 4) * W];

    float vbest;
    if      (t0)        vbest = 0.0f;
    else if (u1 | d1)   vbest = 1.0f;
    else if (u2 | d2v)  vbest = 4.0f;
    else if (u3 | d3)   vbest = 9.0f;
    else if (u4 | d4)   vbest = 16.0f;
    else {
        vbest = INFINITY;
        for (int r = 5; r < H; ++r) {
            const int hu = h - r;
            const int hd = h + r;
            bool found = false;
            if (hu >= 0 && tcol[hu * W] != 0) found = true;
            if (hd < H  && tcol[hd * W] != 0) found = true;
            if (found) { vbest = (float)(r * r); break; }
        }
    }
    s[wo] = vbest;
    __syncthreads();

    // --- 2. Pruned horizontal min search over smem ---
    float best = vbest;
    for (int r = 1; r < W; ++r) {
        const float rr = (float)(r * r);
        if (rr >= best) break;
        const int lo = wo - r;
        const int hi = wo + r;
        if (lo >= 0) best = fminf(best, s[lo] + rr);
        if (hi < W)  best = fminf(best, s[hi] + rr);
    }

    // --- 3. Fused loss ---
    const float d = sqrtf(best);
    const float p = 1.0f / (1.0f + __expf(-x));
    float contrib = p * d + LAMBDA * (1.0f - p);

    #pragma unroll
    for (int off = 16; off > 0; off >>= 1)
        contrib += __shfl_down_sync(0xFFFFFFFFu, contrib, off);

    const int lane = wo & 31;
    const int wid  = wo >> 5;
    if (lane == 0) warp_sums[wid] = contrib;
    __syncthreads();

    if (wid == 0 && lane == 0) {
        float v = 0.0f;
        #pragma unroll
        for (int i = 0; i < W / 32; ++i) v += warp_sums[i];
        atomicAdd(&g_acc, (double)v);
        __threadfence();
        const unsigned int done = atomicAdd(&g_count, 1u);
        if (done == NROWS - 1) {
            // All blocks' adds are visible (each fenced before incrementing).
            out[0] = (float)(g_acc / (double)NPIX);
            // Reset for next graph replay (deterministic state).
            g_acc = 0.0;
            g_count = 0u;
        }
    }
}

extern "C" void kernel_launch(void* const* d_in, const int* in_sizes, int n_in,
                              void* d_out, int out_size)
{
    const float* logits  = (const float*)d_in[0];
    const int*   targets = (const int*)d_in[1];
    float*       out     = (float*)d_out;

    (void)in_sizes; (void)n_in; (void)out_size;

    edt_fused_loss_kernel<<<NROWS, W>>>(logits, targets, out);
}

// round 4
// speedup vs baseline: 4.7555x; 1.2263x over previous
#include <cuda_runtime.h>
#include <math.h>

// Problem constants (fixed by setup_inputs)
#define B 4
#define H 320
#define W 320
#define NPIX   (B * H * W)
#define TILE   8                      // rows per block
#define HALO   8                      // staged halo above/below
#define NSTAGE (TILE + 2 * HALO)      // 24 staged rows -> 24-bit column mask
#define NBLOCKS (B * H / TILE)        // 160
#define LAMBDA 1.0f

__device__ double g_acc;
__device__ unsigned int g_count;

// ---------------------------------------------------------------------------
// One block per 8-row strip of one image; 320 threads (one per column).
//  1. Each thread folds 24 staged target rows into a 24-bit seed mask
//     (24 independent coalesced LDG, then pure-ALU vertical resolve via
//     clz/ffs for all 8 pixels -> effective vertical window >= +-8;
//     fallback global loop has P ~ 1e-5 per pixel).
//  2. g2 for all 8 rows -> smem, ONE barrier, then 8 pruned horizontal
//     searches per thread, loss accumulated in a register.
//  3. One block reduction + one atomicAdd per 2560 pixels; last block
//     finalizes the mean and resets globals (graph-replay safe).
// ---------------------------------------------------------------------------
__global__ void __launch_bounds__(W)
edt_tile_loss_kernel(const float* __restrict__ logits,
                     const int*   __restrict__ targets,
                     float*       __restrict__ out)
{
    __shared__ float s_g2[TILE][W];
    __shared__ float warp_sums[W / 32];

    const int tile = blockIdx.x;            // 0 .. NBLOCKS-1
    const int b    = tile / (H / TILE);
    const int h0   = (tile % (H / TILE)) * TILE;   // first row of strip
    const int wo   = threadIdx.x;                  // column
    const size_t img_base = (size_t)b * H * W;

    const int*   tcol = targets + img_base + wo;
    const float* lcol = logits  + img_base + wo;

    // --- logits for my 8 pixels (independent, issue early) ---
    float xv[TILE];
    #pragma unroll
    for (int j = 0; j < TILE; ++j)
        xv[j] = lcol[(h0 + j) * W];

    // --- build 24-bit column seed mask (rows h0-HALO .. h0+TILE+HALO-1) ---
    unsigned int mask = 0u;
    #pragma unroll
    for (int r = 0; r < NSTAGE; ++r) {
        const int hh = h0 - HALO + r;
        int v = 0;
        if (hh >= 0 && hh < H) v = tcol[hh * W];
        mask |= (unsigned int)(v != 0) << r;
    }

    // --- vertical resolve per pixel (pure ALU) ---
    #pragma unroll
    for (int j = 0; j < TILE; ++j) {
        const int c = j + HALO;                       // staged index of pixel row
        const unsigned int below = mask & ((1u << (c + 1)) - 1u);  // bits <= c
        const unsigned int above = mask >> c;                      // bits >= c
        int d_up = 1 << 20, d_dn = 1 << 20;
        if (below) d_up = c - (31 - __clz(below));
        if (above) d_dn = __ffs(above) - 1;
        int v = min(d_up, d_dn);
        float g2;
        if (mask != 0u) {
            g2 = (float)(v * v);
        } else {
            // Fallback: no seed in the staged window (astronomically rare).
            const int h = h0 + j;
            g2 = INFINITY;
            for (int r = HALO + 1; r < H; ++r) {
                const int hu = h - r, hd = h + r;
                bool found = false;
                if (hu >= 0 && tcol[hu * W] != 0) found = true;
                if (hd < H  && tcol[hd * W] != 0) found = true;
                if (found) { g2 = (float)(r * r); break; }
            }
        }
        s_g2[j][wo] = g2;
    }
    __syncthreads();

    // --- horizontal pruned search + fused loss for my 8 pixels ---
    float acc = 0.0f;
    #pragma unroll
    for (int j = 0; j < TILE; ++j) {
        const float* s = s_g2[j];
        float best = s[wo];
        for (int r = 1; r < W; ++r) {
            const float rr = (float)(r * r);
            if (rr >= best) break;
            const int lo = wo - r;
            const int hi = wo + r;
            if (lo >= 0) best = fminf(best, s[lo] + rr);
            if (hi < W)  best = fminf(best, s[hi] + rr);
        }
        const float d = sqrtf(best);
        const float p = 1.0f / (1.0f + __expf(-xv[j]));
        acc += p * d + LAMBDA * (1.0f - p);
    }

    // --- block reduce + global accumulate ---
    #pragma unroll
    for (int off = 16; off > 0; off >>= 1)
        acc += __shfl_down_sync(0xFFFFFFFFu, acc, off);

    const int lane = wo & 31;
    const int wid  = wo >> 5;
    if (lane == 0) warp_sums[wid] = acc;
    __syncthreads();

    if (wid == 0 && lane == 0) {
        float v = 0.0f;
        #pragma unroll
        for (int i = 0; i < W / 32; ++i) v += warp_sums[i];
        atomicAdd(&g_acc, (double)v);
        __threadfence();
        const unsigned int done = atomicAdd(&g_count, 1u);
        if (done == NBLOCKS - 1) {
            out[0] = (float)(g_acc / (double)NPIX);
            g_acc = 0.0;
            g_count = 0u;
        }
    }
}

extern "C" void kernel_launch(void* const* d_in, const int* in_sizes, int n_in,
                              void* d_out, int out_size)
{
    const float* logits  = (const float*)d_in[0];
    const int*   targets = (const int*)d_in[1];
    float*       out     = (float*)d_out;

    (void)in_sizes; (void)n_in; (void)out_size;

    edt_tile_loss_kernel<<<NBLOCKS, W>>>(logits, targets, out);
}